// round 14
// baseline (speedup 1.0000x reference)
#include <cuda_runtime.h>
#include <math.h>

#define NB 2
#define NS 2048
#define ND 1024
#define NH 16
#define NHD 64
#define MTOT (NB * NS)   // 4096

// Scratch (allocation-free rule: __device__ globals)
__device__ float g_q[NB * NH * NS * NHD];    // [B,H,S,HD]
__device__ float g_k[NB * NH * NS * NHD];    // [B,H,S,HD]
__device__ float g_v[NB * NH * NHD * NS];    // [B,H,HD,S]  (transposed!)
__device__ float g_ctx[NB * NS * ND];        // tf32-rounded, permk'd columns
__device__ float g_xr[MTOT * ND];            // x, tf32-rounded, permk'd columns
__device__ float g_wr[4][ND * ND];           // W^T, tf32-rounded, permk'd cols

// ---------------------------------------------------------------------------
// helpers
// ---------------------------------------------------------------------------
__device__ __forceinline__ float f2tf32(float x) {
    unsigned r;
    asm("cvt.rna.tf32.f32 %0, %1;" : "=r"(r) : "f"(x));
    return __uint_as_float(r);
}

__device__ __forceinline__ void mma_tf32(float (&c)[4], unsigned a0, unsigned a1,
                                         unsigned a2, unsigned a3, unsigned b0,
                                         unsigned b1) {
    asm volatile(
        "mma.sync.aligned.m16n8k8.row.col.f32.tf32.tf32.f32 "
        "{%0,%1,%2,%3}, {%4,%5,%6,%7}, {%8,%9}, {%0,%1,%2,%3};\n"
        : "+f"(c[0]), "+f"(c[1]), "+f"(c[2]), "+f"(c[3])
        : "r"(a0), "r"(a1), "r"(a2), "r"(a3), "r"(b0), "r"(b1));
}

__device__ __forceinline__ unsigned smaddr(const void* p) {
    return (unsigned)__cvta_generic_to_shared(p);
}
#define CP_ASYNC16(dst, src) \
    asm volatile("cp.async.cg.shared.global [%0], [%1], 16;\n" ::"r"(dst), "l"(src))
#define CP_COMMIT() asm volatile("cp.async.commit_group;\n")
#define CP_WAIT(n) asm volatile("cp.async.wait_group %0;\n" ::"n"(n))

// interleave k within 8-blocks so fragment pairs (k, k+4) are adjacent.
__device__ __forceinline__ int permk(int c) {
    return (c & ~7) | ((c & 3) << 1) | ((c >> 2) & 1);
}

// ---------------------------------------------------------------------------
// Prep kernels: tf32-round + permute (x) / transpose+round+permute (W)
// ---------------------------------------------------------------------------
__global__ void __launch_bounds__(256)
round_x_kernel(const float* __restrict__ x) {
    const int f4 = blockIdx.x * 256 + threadIdx.x;
    const int base = f4 * 4;
    float4 v = *(const float4*)&x[base];
    g_xr[permk(base + 0)] = f2tf32(v.x);
    g_xr[permk(base + 1)] = f2tf32(v.y);
    g_xr[permk(base + 2)] = f2tf32(v.z);
    g_xr[permk(base + 3)] = f2tf32(v.w);
}

__global__ void __launch_bounds__(256)
round_w_kernel(const float* __restrict__ Wq, const float* __restrict__ Wk,
               const float* __restrict__ Wv, const float* __restrict__ Wo) {
    __shared__ float t[32][33];
    const float* W;
    if (blockIdx.z == 0) W = Wq;
    else if (blockIdx.z == 1) W = Wk;
    else if (blockIdx.z == 2) W = Wv;
    else W = Wo;
    float* out = &g_wr[blockIdx.z][0];

    const int k0 = blockIdx.x * 32, n0 = blockIdx.y * 32;
    const int tx = threadIdx.x, ty = threadIdx.y;
#pragma unroll
    for (int i = 0; i < 4; i++)
        t[ty + i * 8][tx] = W[(size_t)(k0 + ty + i * 8) * ND + n0 + tx];
    __syncthreads();
#pragma unroll
    for (int i = 0; i < 4; i++)
        out[(size_t)(n0 + ty + i * 8) * ND + k0 + permk(tx)] =
            f2tf32(t[tx][ty + i * 8]);
}

// ---------------------------------------------------------------------------
// 256x128x32 TF32 GEMM tile (round-12 proven version).
// ---------------------------------------------------------------------------
#define GEMM_ASTG (256 * 40)
#define GEMM_BSTG (128 * 40)
#define GEMM_STG (GEMM_ASTG + GEMM_BSTG)
#define GEMM_SMEM_FLOATS (2 * GEMM_STG)
#define GEMM_SMEM_BYTES (GEMM_SMEM_FLOATS * 4)

__device__ __forceinline__ void gemm_load_stage(const float* __restrict__ A,
                                                const float* __restrict__ Bt,
                                                float* stage, int mBase,
                                                int nBase, int k0, int tid) {
    float* sA = stage;
    float* sB = stage + GEMM_ASTG;
#pragma unroll
    for (int i = 0; i < 8; i++) {
        const int f4 = tid + i * 256;
        const int m = f4 >> 3, c4 = (f4 & 7) * 4;
        CP_ASYNC16(smaddr(&sA[m * 40 + c4]),
                   &A[(size_t)(mBase + m) * ND + k0 + c4]);
    }
#pragma unroll
    for (int i = 0; i < 4; i++) {
        const int f4 = tid + i * 256;
        const int m = f4 >> 3, c4 = (f4 & 7) * 4;
        CP_ASYNC16(smaddr(&sB[m * 40 + c4]),
                   &Bt[(size_t)(nBase + m) * ND + k0 + c4]);
    }
    CP_COMMIT();
}

__device__ __forceinline__ void sgemm_mma(const float* __restrict__ A,
                                          const float* __restrict__ Bt,
                                          float (&acc)[4][8][4]) {
    extern __shared__ float gsm[];

    const int tid = threadIdx.x;
    const int lane = tid & 31;
    const int wid = tid >> 5;
    const int warpM = wid >> 1;
    const int warpN = wid & 1;
    const int gid = lane >> 2;
    const int tig = lane & 3;
    const int mBase = blockIdx.y * 256;
    const int nBase = blockIdx.x * 128;

    gemm_load_stage(A, Bt, gsm, mBase, nBase, 0, tid);

    for (int k0 = 0; k0 < ND; k0 += 32) {
        const int st = (k0 >> 5) & 1;
        CP_WAIT(0);
        __syncthreads();
        if (k0 + 32 < ND)
            gemm_load_stage(A, Bt, gsm + (st ^ 1) * GEMM_STG, mBase, nBase,
                            k0 + 32, tid);

        const float* As = gsm + st * GEMM_STG;
        const float* Bs = As + GEMM_ASTG;
#pragma unroll
        for (int ks = 0; ks < 32; ks += 8) {
            unsigned bf[8][2];
#pragma unroll
            for (int nt = 0; nt < 8; nt++) {
                float2 bb = *(const float2*)&Bs[(warpN * 64 + nt * 8 + gid) * 40 + ks + 2 * tig];
                bf[nt][0] = __float_as_uint(bb.x);
                bf[nt][1] = __float_as_uint(bb.y);
            }
#pragma unroll
            for (int mt = 0; mt < 4; mt++) {
                const int m = warpM * 64 + mt * 16;
                float2 lo = *(const float2*)&As[(m + gid) * 40 + ks + 2 * tig];
                float2 hi = *(const float2*)&As[(m + gid + 8) * 40 + ks + 2 * tig];
                const unsigned a0 = __float_as_uint(lo.x);
                const unsigned a1 = __float_as_uint(hi.x);
                const unsigned a2 = __float_as_uint(lo.y);
                const unsigned a3 = __float_as_uint(hi.y);
#pragma unroll
                for (int nt = 0; nt < 8; nt++)
                    mma_tf32(acc[mt][nt], a0, a1, a2, a3, bf[nt][0], bf[nt][1]);
            }
        }
    }
}

// QKV projection. Q/K in [B,H,S,HD]; V stored TRANSPOSED [B,H,HD,S]. z=3.
// V epilogue stages through smem for coalesced STG.128 (4B-scatter fix).
__global__ void __launch_bounds__(256, 1)
qkv_proj_kernel(const float* __restrict__ bq, const float* __restrict__ bk,
                const float* __restrict__ bv) {
    extern __shared__ float epi[];
    const float* Bt;
    const float* bias;
    float sc;
    if (blockIdx.z == 0) { Bt = g_wr[0]; bias = bq; sc = 0.125f; }
    else if (blockIdx.z == 1) { Bt = g_wr[1]; bias = bk; sc = 1.0f; }
    else { Bt = g_wr[2]; bias = bv; sc = 1.0f; }

    float acc[4][8][4] = {};
    sgemm_mma(g_xr, Bt, acc);

    const int tid = threadIdx.x;
    const int lane = tid & 31;
    const int wid = tid >> 5;
    const int warpM = wid >> 1, warpN = wid & 1;
    const int gid = lane >> 2, tig = lane & 3;
    const int mBase = blockIdx.y * 256, nBase = blockIdx.x * 128;

    if (blockIdx.z < 2) {
        float* out = (blockIdx.z == 0) ? g_q : g_k;
#pragma unroll
        for (int mt = 0; mt < 4; mt++) {
#pragma unroll
            for (int nt = 0; nt < 8; nt++) {
                const int c = nBase + warpN * 64 + nt * 8 + tig * 2;
                const int h = c >> 6, hd = c & 63;
                const float b0v = bias[c], b1v = bias[c + 1];
#pragma unroll
                for (int half = 0; half < 2; half++) {
                    const int r = mBase + warpM * 64 + mt * 16 + gid + half * 8;
                    const int b = r >> 11, s = r & 2047;
                    float2 val;
                    val.x = f2tf32((acc[mt][nt][half * 2 + 0] + b0v) * sc);
                    val.y = f2tf32((acc[mt][nt][half * 2 + 1] + b1v) * sc);
                    *(float2*)&out[(((b * NH + h) * NS + s) << 6) + hd] = val;
                }
            }
        }
    } else {
        // V: stage transposed tile [hd 64][s 256] in smem (stride 268 —
        // conflict-free STS), then coalesced STG.128 to g_v[...][hd][s].
        const int bb = mBase >> 11, sBase = mBase & 2047;
#pragma unroll
        for (int half = 0; half < 2; half++) {
            __syncthreads();   // mainloop smem reads / prior half done
            if (warpN == half) {
#pragma unroll
                for (int nt = 0; nt < 8; nt++) {
                    const int rl = nt * 8 + tig * 2;   // local hd row (even)
                    const int c = nBase + half * 64 + rl;
                    const float b0v = bias[c], b1v = bias[c + 1];
#pragma unroll
                    for (int mt = 0; mt < 4; mt++) {
#pragma unroll
                        for (int hm = 0; hm < 2; hm++) {
                            const int m = warpM * 64 + mt * 16 + gid + hm * 8;
                            epi[rl * 268 + m] =
                                f2tf32(acc[mt][nt][hm * 2 + 0] + b0v);
                            epi[(rl + 1) * 268 + m] =
                                f2tf32(acc[mt][nt][hm * 2 + 1] + b1v);
                        }
                    }
                }
            }
            __syncthreads();
            const int h = (nBase >> 6) + half;
            float* vout = &g_v[(size_t)((bb * NH + h) * NHD) * NS];
#pragma unroll
            for (int i = 0; i < 16; i++) {
                const int idx = tid + i * 256;   // 4096 float4 chunks
                const int r = idx >> 6;          // hd row 0..63
                const int c4 = (idx & 63) * 4;   // s offset within tile
                float4 v;
                v.x = epi[r * 268 + c4 + 0];
                v.y = epi[r * 268 + c4 + 1];
                v.z = epi[r * 268 + c4 + 2];
                v.w = epi[r * 268 + c4 + 3];
                *(float4*)&vout[(size_t)r * NS + sBase + c4] = v;
            }
        }
    }
}

// Output projection: out = ctx @ Wo + bo (ctx pre-rounded/permuted by flash)
__global__ void __launch_bounds__(256, 1)
out_proj_kernel(const float* __restrict__ bo, float* __restrict__ out) {
    float acc[4][8][4] = {};
    sgemm_mma(g_ctx, g_wr[3], acc);

    const int lane = threadIdx.x & 31;
    const int wid = threadIdx.x >> 5;
    const int warpM = wid >> 1, warpN = wid & 1;
    const int gid = lane >> 2, tig = lane & 3;
    const int mBase = blockIdx.y * 256, nBase = blockIdx.x * 128;

#pragma unroll
    for (int mt = 0; mt < 4; mt++) {
#pragma unroll
        for (int nt = 0; nt < 8; nt++) {
            const int c = nBase + warpN * 64 + nt * 8 + tig * 2;
            const float b0v = bo[c], b1v = bo[c + 1];
#pragma unroll
            for (int half = 0; half < 2; half++) {
                const int r = mBase + warpM * 64 + mt * 16 + gid + half * 8;
                float2 val;
                val.x = acc[mt][nt][half * 2 + 0] + b0v;
                val.y = acc[mt][nt][half * 2 + 1] + b1v;
                *(float2*)&out[(size_t)r * ND + c] = val;
            }
        }
    }
}

// ---------------------------------------------------------------------------
// FlashAttention-2, cp.async double-buffered K/V, register softmax.
// ONE barrier per key tile: {wait; sync; prefetch; compute}.
// (round-12 proven version, byte-identical)
// ---------------------------------------------------------------------------
#define FQS 72
#define FQ_OFF 0
#define FK_OFF (128 * FQS)
#define FV_OFF (FK_OFF + 2 * 64 * FQS)
#define F_SMEM_FLOATS (FV_OFF + 2 * 64 * FQS)
#define F_SMEM_BYTES (F_SMEM_FLOATS * 4)

__global__ void __launch_bounds__(256, 2) flash_attn_kernel() {
    extern __shared__ float sm[];
    float* Qs = sm + FQ_OFF;

    const int tid = threadIdx.x;
    const int lane = tid & 31;
    const int wid = tid >> 5;        // 0..7, 16 query rows each
    const int gid = lane >> 2;       // 0..7
    const int tig = lane & 3;        // 0..3

    const int qt = gridDim.x - 1 - blockIdx.x;  // heavy tiles first
    const int h = blockIdx.y, b = blockIdx.z;
    const int bhBase = ((b * NH + h) * NS) << 6;
    const float* Qg = g_q + bhBase;
    const float* Kg = g_k + bhBase;
    const float* Vgt = g_v + bhBase;  // [HD][S] block

    // prologue: async-load Q tile + K0 + V0 (group 0)
#pragma unroll
    for (int i = 0; i < 8; i++) {
        const int f4 = tid + i * 256;
        const int r = f4 >> 4, c4 = (f4 & 15) * 4;
        CP_ASYNC16(smaddr(&Qs[r * FQS + c4]), &Qg[((qt * 128 + r) << 6) + c4]);
    }
#pragma unroll
    for (int i = 0; i < 4; i++) {
        const int f4 = tid + i * 256;
        const int r = f4 >> 4, c4 = (f4 & 15) * 4;
        CP_ASYNC16(smaddr(&sm[FK_OFF + r * FQS + c4]), &Kg[(r << 6) + c4]);
        CP_ASYNC16(smaddr(&sm[FV_OFF + r * FQS + c4]), &Vgt[r * NS + c4]);
    }
    CP_COMMIT();

    float o[8][4] = {};
    float m0 = -1e30f, m1 = -1e30f, l0 = 0.0f, l1 = 0.0f;
    const int wBase = wid * 16;
    const int rowG0 = qt * 128 + wBase + gid;
    const int ktMax = 2 * qt + 1;

    for (int kt = 0; kt <= ktMax; kt++) {
        const int st = kt & 1;
        CP_WAIT(0);
        __syncthreads();
        if (kt < ktMax) {
            float* Kn = sm + FK_OFF + (st ^ 1) * 64 * FQS;
            float* Vn = sm + FV_OFF + (st ^ 1) * 64 * FQS;
            const float* Kgn = Kg + (((kt + 1) * 64) << 6);
            const float* Vgn = Vgt + (kt + 1) * 64;
#pragma unroll
            for (int i = 0; i < 4; i++) {
                const int f4 = tid + i * 256;
                const int r = f4 >> 4, c4 = (f4 & 15) * 4;
                CP_ASYNC16(smaddr(&Kn[r * FQS + c4]), &Kgn[(r << 6) + c4]);
                CP_ASYNC16(smaddr(&Vn[r * FQS + c4]), &Vgn[r * NS + c4]);
            }
            CP_COMMIT();
        }

        const float* Ks = sm + FK_OFF + st * 64 * FQS;
        const float* Vs = sm + FV_OFF + st * 64 * FQS;

        // Warp-level skip: rows of this warp all above the key range -> masked
        const bool active = (qt * 128 + wBase + 15) >= kt * 64;
        if (active) {
            // ---- S = Q @ K^T ----
            float s[8][4] = {};
#pragma unroll
            for (int kb = 0; kb < 8; kb++) {
                float2 qlo = *(const float2*)&Qs[(wBase + gid) * FQS + kb * 8 + 2 * tig];
                float2 qhi = *(const float2*)&Qs[(wBase + gid + 8) * FQS + kb * 8 + 2 * tig];
                const unsigned a0 = __float_as_uint(qlo.x);
                const unsigned a1 = __float_as_uint(qhi.x);
                const unsigned a2 = __float_as_uint(qlo.y);
                const unsigned a3 = __float_as_uint(qhi.y);
#pragma unroll
                for (int nt = 0; nt < 8; nt++) {
                    float2 bb = *(const float2*)&Ks[(nt * 8 + gid) * FQS + kb * 8 + 2 * tig];
                    mma_tf32(s[nt], a0, a1, a2, a3,
                             __float_as_uint(bb.x), __float_as_uint(bb.y));
                }
            }

            // ---- causal mask (last two kt tiles only) ----
            if (kt >= 2 * qt) {
#pragma unroll
                for (int nt = 0; nt < 8; nt++) {
                    const int col = kt * 64 + nt * 8 + 2 * tig;
                    if (col > rowG0) s[nt][0] = -1e30f;
                    if (col + 1 > rowG0) s[nt][1] = -1e30f;
                    if (col > rowG0 + 8) s[nt][2] = -1e30f;
                    if (col + 1 > rowG0 + 8) s[nt][3] = -1e30f;
                }
            }

            // ---- online softmax (registers + quad shuffles) ----
            float mx0 = -1e30f, mx1 = -1e30f;
#pragma unroll
            for (int nt = 0; nt < 8; nt++) {
                mx0 = fmaxf(mx0, fmaxf(s[nt][0], s[nt][1]));
                mx1 = fmaxf(mx1, fmaxf(s[nt][2], s[nt][3]));
            }
            mx0 = fmaxf(mx0, __shfl_xor_sync(0xffffffffu, mx0, 1));
            mx0 = fmaxf(mx0, __shfl_xor_sync(0xffffffffu, mx0, 2));
            mx1 = fmaxf(mx1, __shfl_xor_sync(0xffffffffu, mx1, 1));
            mx1 = fmaxf(mx1, __shfl_xor_sync(0xffffffffu, mx1, 2));
            const float mn0 = fmaxf(m0, mx0);
            const float mn1 = fmaxf(m1, mx1);
            const float al0 = __expf(m0 - mn0);
            const float al1 = __expf(m1 - mn1);
            m0 = mn0; m1 = mn1;
            float sum0 = 0.0f, sum1 = 0.0f;
#pragma unroll
            for (int nt = 0; nt < 8; nt++) {
                float p0 = __expf(s[nt][0] - mn0);
                float p1 = __expf(s[nt][1] - mn0);
                float p2 = __expf(s[nt][2] - mn1);
                float p3 = __expf(s[nt][3] - mn1);
                sum0 += p0 + p1;
                sum1 += p2 + p3;
                s[nt][0] = f2tf32(p0);
                s[nt][1] = f2tf32(p1);
                s[nt][2] = f2tf32(p2);
                s[nt][3] = f2tf32(p3);
            }
            sum0 += __shfl_xor_sync(0xffffffffu, sum0, 1);
            sum0 += __shfl_xor_sync(0xffffffffu, sum0, 2);
            sum1 += __shfl_xor_sync(0xffffffffu, sum1, 1);
            sum1 += __shfl_xor_sync(0xffffffffu, sum1, 2);
            l0 = l0 * al0 + sum0;
            l1 = l1 * al1 + sum1;

            // ---- O = O*alpha + P @ V  (Vt[hd][key], float2 b-frags) ----
#pragma unroll
            for (int nt = 0; nt < 8; nt++) {
                o[nt][0] *= al0; o[nt][1] *= al0;
                o[nt][2] *= al1; o[nt][3] *= al1;
            }
#pragma unroll
            for (int kb = 0; kb < 8; kb++) {
                const unsigned a0 = __float_as_uint(s[kb][0]);
                const unsigned a1 = __float_as_uint(s[kb][2]);
                const unsigned a2 = __float_as_uint(s[kb][1]);
                const unsigned a3 = __float_as_uint(s[kb][3]);
#pragma unroll
                for (int nt = 0; nt < 8; nt++) {
                    float2 bb = *(const float2*)&Vs[(nt * 8 + gid) * FQS + kb * 8 + 2 * tig];
                    mma_tf32(o[nt], a0, a1, a2, a3,
                             __float_as_uint(bb.x), __float_as_uint(bb.y));
                }
            }
        }
    }

    // ---- normalize, round, store ctx permk'd in [B,S,D] for out_proj ----
    const float i0 = 1.0f / l0;
    const float i1 = 1.0f / l1;
    const int colBase = (h << 6) + 2 * tig;
    float* row0 = &g_ctx[(size_t)(b * NS + rowG0) * ND];
    float* row1 = &g_ctx[(size_t)(b * NS + rowG0 + 8) * ND];
#pragma unroll
    for (int nt = 0; nt < 8; nt++) {
        const int c = colBase + nt * 8;
        row0[permk(c)] = f2tf32(o[nt][0] * i0);
        row0[permk(c + 1)] = f2tf32(o[nt][1] * i0);
        row1[permk(c)] = f2tf32(o[nt][2] * i1);
        row1[permk(c + 1)] = f2tf32(o[nt][3] * i1);
    }
}

extern "C" void kernel_launch(void* const* d_in, const int* in_sizes, int n_in,
                              void* d_out, int out_size) {
    const float* x = (const float*)d_in[0];
    const float* Wq = (const float*)d_in[1];
    const float* bq = (const float*)d_in[2];
    const float* Wk = (const float*)d_in[3];
    const float* bk = (const float*)d_in[4];
    const float* Wv = (const float*)d_in[5];
    const float* bv = (const float*)d_in[6];
    const float* Wo = (const float*)d_in[7];
    const float* bo = (const float*)d_in[8];
    float* out = (float*)d_out;

    cudaFuncSetAttribute(flash_attn_kernel,
                         cudaFuncAttributeMaxDynamicSharedMemorySize,
                         F_SMEM_BYTES);
    cudaFuncSetAttribute(qkv_proj_kernel,
                         cudaFuncAttributeMaxDynamicSharedMemorySize,
                         GEMM_SMEM_BYTES);
    cudaFuncSetAttribute(out_proj_kernel,
                         cudaFuncAttributeMaxDynamicSharedMemorySize,
                         GEMM_SMEM_BYTES);

    // Prep: round + permute x; transpose + round + permute all W
    round_x_kernel<<<MTOT * ND / 1024, 256>>>(x);
    dim3 gw(ND / 32, ND / 32, 4);
    round_w_kernel<<<gw, dim3(32, 8)>>>(Wq, Wk, Wv, Wo);

    dim3 g1(ND / 128, MTOT / 256, 3);
    qkv_proj_kernel<<<g1, 256, GEMM_SMEM_BYTES>>>(bq, bk, bv);

    dim3 g2(NS / 128, NH, NB);
    flash_attn_kernel<<<g2, 256, F_SMEM_BYTES>>>();

    dim3 g3(ND / 128, MTOT / 256);
    out_proj_kernel<<<g3, 256, GEMM_SMEM_BYTES>>>(bo, out);
}

// round 15
// speedup vs baseline: 1.6479x; 1.6479x over previous
#include <cuda_runtime.h>
#include <cuda_fp16.h>
#include <math.h>

#define NB 2
#define NS 2048
#define ND 1024
#define NH 16
#define NHD 64
#define MTOT (NB * NS)   // 4096

// Scratch (allocation-free rule: __device__ globals). All half, permh'd k.
__device__ __half h_q[NB * NH * NS * NHD];    // [B,H,S, permh(HD)]
__device__ __half h_k[NB * NH * NS * NHD];    // [B,H,S, permh(HD)]
__device__ __half h_v[NB * NH * NHD * NS];    // [B,H,HD, permh(S)]
__device__ __half h_ctx[NB * NS * ND];        // [M, permh(ND)]
__device__ __half h_xr[MTOT * ND];            // [M, permh(ND)]
__device__ __half h_wr[4][ND * ND];           // [N, permh(ND)] (W^T)

// ---------------------------------------------------------------------------
// helpers
// ---------------------------------------------------------------------------
__device__ __forceinline__ void mma_fp16(float (&c)[4], unsigned a0, unsigned a1,
                                         unsigned a2, unsigned a3, unsigned b0,
                                         unsigned b1) {
    asm volatile(
        "mma.sync.aligned.m16n8k16.row.col.f32.f16.f16.f32 "
        "{%0,%1,%2,%3}, {%4,%5,%6,%7}, {%8,%9}, {%0,%1,%2,%3};\n"
        : "+f"(c[0]), "+f"(c[1]), "+f"(c[2]), "+f"(c[3])
        : "r"(a0), "r"(a1), "r"(a2), "r"(a3), "r"(b0), "r"(b1));
}

__device__ __forceinline__ unsigned h2u(__half2 h) {
    return *reinterpret_cast<unsigned*>(&h);
}

__device__ __forceinline__ unsigned smaddr(const void* p) {
    return (unsigned)__cvta_generic_to_shared(p);
}
#define CP_ASYNC16(dst, src) \
    asm volatile("cp.async.cg.shared.global [%0], [%1], 16;\n" ::"r"(dst), "l"(src))
#define CP_COMMIT() asm volatile("cp.async.commit_group;\n")
#define CP_WAIT(n) asm volatile("cp.async.wait_group %0;\n" ::"n"(n))

// permh: within each 16-block, place k at position so that the fragment
// quad (2t, 2t+1, 2t+8, 2t+9) for quad-thread t is CONTIGUOUS (4 halves =
// one 8B LDS supplying {reg_k0, reg_k1} of an m16n8k16 fp16 fragment).
__device__ __forceinline__ int permh(int k) {
    return (k & ~15) | ((((k & 7) >> 1)) << 2) | (k & 1) | (((k >> 3) & 1) << 1);
}

// ---------------------------------------------------------------------------
// Prep kernels: fp16-round + permute (x) / transpose+round+permute (W)
// ---------------------------------------------------------------------------
__global__ void __launch_bounds__(256)
round_x_kernel(const float* __restrict__ x) {
    const int base = (blockIdx.x * 256 + threadIdx.x) * 4;
    float4 v = *(const float4*)&x[base];
    h_xr[permh(base + 0)] = __float2half_rn(v.x);
    h_xr[permh(base + 1)] = __float2half_rn(v.y);
    h_xr[permh(base + 2)] = __float2half_rn(v.z);
    h_xr[permh(base + 3)] = __float2half_rn(v.w);
}

__global__ void __launch_bounds__(256)
round_w_kernel(const float* __restrict__ Wq, const float* __restrict__ Wk,
               const float* __restrict__ Wv, const float* __restrict__ Wo) {
    __shared__ float t[32][33];
    const float* W;
    if (blockIdx.z == 0) W = Wq;
    else if (blockIdx.z == 1) W = Wk;
    else if (blockIdx.z == 2) W = Wv;
    else W = Wo;
    __half* out = &h_wr[blockIdx.z][0];

    const int k0 = blockIdx.x * 32, n0 = blockIdx.y * 32;
    const int tx = threadIdx.x, ty = threadIdx.y;
#pragma unroll
    for (int i = 0; i < 4; i++)
        t[ty + i * 8][tx] = W[(size_t)(k0 + ty + i * 8) * ND + n0 + tx];
    __syncthreads();
#pragma unroll
    for (int i = 0; i < 4; i++)
        out[(size_t)(n0 + ty + i * 8) * ND + k0 + permh(tx)] =
            __float2half_rn(t[tx][ty + i * 8]);
}

// ---------------------------------------------------------------------------
// 256x128x32 FP16 GEMM tile, 2-stage cp.async, one barrier per chunk.
// 8 warps 4(M)x2(N); warp tile 64x64; m16n8k16 -> 64 mma per k32 chunk.
// Smem halves: A[2][256][48] | B[2][128][48]  (73.7 KB). 1 CTA/SM.
// Fragment loads: single LDS.64 per {k0,k1} reg pair (permh layout);
// stride 48 halves (24 words) -> conflict-free phases.
// ---------------------------------------------------------------------------
#define GSTRH 48
#define GA_H (256 * GSTRH)
#define GB_H (128 * GSTRH)
#define GST_H (GA_H + GB_H)
#define GEMM_SMEM_BYTES (2 * GST_H * 2)

__device__ __forceinline__ void gemm_load_stage(const __half* __restrict__ A,
                                                const __half* __restrict__ Bt,
                                                __half* stage, int mBase,
                                                int nBase, int k0, int tid) {
    __half* sA = stage;
    __half* sB = stage + GA_H;
#pragma unroll
    for (int i = 0; i < 4; i++) {   // A: 256 rows x 4 chunks(16B)
        const int idx = tid + i * 256;
        const int row = idx >> 2, ch = (idx & 3) * 8;
        CP_ASYNC16(smaddr(&sA[row * GSTRH + ch]),
                   &A[(size_t)(mBase + row) * ND + k0 + ch]);
    }
#pragma unroll
    for (int i = 0; i < 2; i++) {   // B: 128 rows x 4 chunks
        const int idx = tid + i * 256;
        const int row = idx >> 2, ch = (idx & 3) * 8;
        CP_ASYNC16(smaddr(&sB[row * GSTRH + ch]),
                   &Bt[(size_t)(nBase + row) * ND + k0 + ch]);
    }
    CP_COMMIT();
}

__device__ __forceinline__ void sgemm_mma(const __half* __restrict__ A,
                                          const __half* __restrict__ Bt,
                                          float (&acc)[4][8][4]) {
    extern __shared__ __half gsm[];

    const int tid = threadIdx.x;
    const int lane = tid & 31;
    const int wid = tid >> 5;
    const int warpM = wid >> 1;   // 0..3 -> 64 rows each
    const int warpN = wid & 1;    // 0..1 -> 64 cols each
    const int gid = lane >> 2;
    const int tig = lane & 3;
    const int mBase = blockIdx.y * 256;
    const int nBase = blockIdx.x * 128;

    gemm_load_stage(A, Bt, gsm, mBase, nBase, 0, tid);

    for (int k0 = 0; k0 < ND; k0 += 32) {
        const int st = (k0 >> 5) & 1;
        CP_WAIT(0);
        __syncthreads();
        if (k0 + 32 < ND)
            gemm_load_stage(A, Bt, gsm + (st ^ 1) * GST_H, mBase, nBase,
                            k0 + 32, tid);

        const __half* As = gsm + st * GST_H;
        const __half* Bs = As + GA_H;
#pragma unroll
        for (int ks = 0; ks < 32; ks += 16) {
            uint2 bf[8];
#pragma unroll
            for (int nt = 0; nt < 8; nt++)
                bf[nt] = *(const uint2*)&Bs[(warpN * 64 + nt * 8 + gid) * GSTRH + ks + 4 * tig];
#pragma unroll
            for (int mt = 0; mt < 4; mt++) {
                const int m = warpM * 64 + mt * 16;
                uint2 lo = *(const uint2*)&As[(m + gid) * GSTRH + ks + 4 * tig];
                uint2 hi = *(const uint2*)&As[(m + gid + 8) * GSTRH + ks + 4 * tig];
#pragma unroll
                for (int nt = 0; nt < 8; nt++)
                    mma_fp16(acc[mt][nt], lo.x, hi.x, lo.y, hi.y,
                             bf[nt].x, bf[nt].y);
            }
        }
    }
}

// QKV projection. Q/K half [B,H,S,permh(HD)]; V half TRANSPOSED
// [B,H,HD,permh(S)]. gridDim.z = 3. Q pre-scaled by 0.125.
__global__ void __launch_bounds__(256, 1)
qkv_proj_kernel(const float* __restrict__ bq, const float* __restrict__ bk,
                const float* __restrict__ bv) {
    const __half* Bt;
    const float* bias;
    float sc;
    if (blockIdx.z == 0) { Bt = h_wr[0]; bias = bq; sc = 0.125f; }
    else if (blockIdx.z == 1) { Bt = h_wr[1]; bias = bk; sc = 1.0f; }
    else { Bt = h_wr[2]; bias = bv; sc = 1.0f; }

    float acc[4][8][4] = {};
    sgemm_mma(h_xr, Bt, acc);

    const int lane = threadIdx.x & 31;
    const int wid = threadIdx.x >> 5;
    const int warpM = wid >> 1, warpN = wid & 1;
    const int gid = lane >> 2, tig = lane & 3;
    const int mBase = blockIdx.y * 256, nBase = blockIdx.x * 128;

    if (blockIdx.z < 2) {
        __half* out = (blockIdx.z == 0) ? h_q : h_k;
#pragma unroll
        for (int mt = 0; mt < 4; mt++) {
#pragma unroll
            for (int nt = 0; nt < 8; nt++) {
                const int c = nBase + warpN * 64 + nt * 8 + tig * 2;
                const int h = c >> 6, hd = c & 63;
                const float b0v = bias[c], b1v = bias[c + 1];
#pragma unroll
                for (int half_ = 0; half_ < 2; half_++) {
                    const int r = mBase + warpM * 64 + mt * 16 + gid + half_ * 8;
                    const int b = r >> 11, s = r & 2047;
                    __half2 val = __floats2half2_rn(
                        (acc[mt][nt][half_ * 2 + 0] + b0v) * sc,
                        (acc[mt][nt][half_ * 2 + 1] + b1v) * sc);
                    *(__half2*)&out[(((b * NH + h) * NS + s) << 6) + permh(hd)] =
                        val;
                }
            }
        }
    } else {
        // V: transposed store h_v[((b*NH+h)*NHD + hd)*NS + permh(s)]
#pragma unroll
        for (int mt = 0; mt < 4; mt++) {
#pragma unroll
            for (int nt = 0; nt < 8; nt++) {
                const int c = nBase + warpN * 64 + nt * 8 + tig * 2;
                const int h = c >> 6, hd = c & 63;
                const float b0v = bias[c], b1v = bias[c + 1];
#pragma unroll
                for (int half_ = 0; half_ < 2; half_++) {
                    const int r = mBase + warpM * 64 + mt * 16 + gid + half_ * 8;
                    const int b = r >> 11, s = r & 2047;
                    __half* base =
                        &h_v[(size_t)((b * NH + h) * NHD + hd) * NS + permh(s)];
                    base[0] = __float2half_rn(acc[mt][nt][half_ * 2 + 0] + b0v);
                    base[NS] = __float2half_rn(acc[mt][nt][half_ * 2 + 1] + b1v);
                }
            }
        }
    }
}

// Output projection: out = ctx @ Wo + bo  (f32 output)
__global__ void __launch_bounds__(256, 1)
out_proj_kernel(const float* __restrict__ bo, float* __restrict__ out) {
    float acc[4][8][4] = {};
    sgemm_mma(h_ctx, h_wr[3], acc);

    const int lane = threadIdx.x & 31;
    const int wid = threadIdx.x >> 5;
    const int warpM = wid >> 1, warpN = wid & 1;
    const int gid = lane >> 2, tig = lane & 3;
    const int mBase = blockIdx.y * 256, nBase = blockIdx.x * 128;

#pragma unroll
    for (int mt = 0; mt < 4; mt++) {
#pragma unroll
        for (int nt = 0; nt < 8; nt++) {
            const int c = nBase + warpN * 64 + nt * 8 + tig * 2;
            const float b0v = bo[c], b1v = bo[c + 1];
#pragma unroll
            for (int half_ = 0; half_ < 2; half_++) {
                const int r = mBase + warpM * 64 + mt * 16 + gid + half_ * 8;
                float2 val;
                val.x = acc[mt][nt][half_ * 2 + 0] + b0v;
                val.y = acc[mt][nt][half_ * 2 + 1] + b1v;
                *(float2*)&out[(size_t)r * ND + c] = val;
            }
        }
    }
}

// ---------------------------------------------------------------------------
// FlashAttention-2 fp16: round-12 structure, m16n8k16 mma (half the mma +
// LDS count). Q[128][80] | K[2][64][80] | V[2][64][80] halves = 60 KB,
// 2 CTAs/SM. Stride 80 halves -> conflict-free LDS.64 phases.
// ---------------------------------------------------------------------------
#define FQH 80
#define FQ_OFF 0
#define FK_OFF (128 * FQH)
#define FV_OFF (FK_OFF + 2 * 64 * FQH)
#define F_SMEM_HALVES (FV_OFF + 2 * 64 * FQH)
#define F_SMEM_BYTES (F_SMEM_HALVES * 2)

__global__ void __launch_bounds__(256, 2) flash_attn_kernel() {
    extern __shared__ __half smh[];
    __half* Qs = smh + FQ_OFF;

    const int tid = threadIdx.x;
    const int lane = tid & 31;
    const int wid = tid >> 5;        // 0..7, 16 query rows each
    const int gid = lane >> 2;       // 0..7
    const int tig = lane & 3;        // 0..3

    const int qt = gridDim.x - 1 - blockIdx.x;  // heavy tiles first
    const int h = blockIdx.y, b = blockIdx.z;
    const int bhBase = ((b * NH + h) * NS) << 6;
    const __half* Qg = h_q + bhBase;
    const __half* Kg = h_k + bhBase;
    const __half* Vgt = h_v + bhBase;  // [HD][permh(S)] block

    // prologue: async-load Q tile + K0 + V0 (one group)
#pragma unroll
    for (int i = 0; i < 4; i++) {
        const int idx = tid + i * 256;
        const int r = idx >> 3, ch = (idx & 7) * 8;
        CP_ASYNC16(smaddr(&Qs[r * FQH + ch]), &Qg[((qt * 128 + r) << 6) + ch]);
    }
#pragma unroll
    for (int i = 0; i < 2; i++) {
        const int idx = tid + i * 256;
        const int r = idx >> 3, ch = (idx & 7) * 8;
        CP_ASYNC16(smaddr(&smh[FK_OFF + r * FQH + ch]), &Kg[(r << 6) + ch]);
        CP_ASYNC16(smaddr(&smh[FV_OFF + r * FQH + ch]), &Vgt[r * NS + ch]);
    }
    CP_COMMIT();

    float o[8][4] = {};
    float m0 = -1e30f, m1 = -1e30f, l0 = 0.0f, l1 = 0.0f;
    const int wBase = wid * 16;
    const int rowG0 = qt * 128 + wBase + gid;
    const int ktMax = 2 * qt + 1;

    for (int kt = 0; kt <= ktMax; kt++) {
        const int st = kt & 1;
        CP_WAIT(0);
        __syncthreads();
        if (kt < ktMax) {
            __half* Kn = smh + FK_OFF + (st ^ 1) * 64 * FQH;
            __half* Vn = smh + FV_OFF + (st ^ 1) * 64 * FQH;
            const __half* Kgn = Kg + (((kt + 1) * 64) << 6);
            const __half* Vgn = Vgt + (kt + 1) * 64;
#pragma unroll
            for (int i = 0; i < 2; i++) {
                const int idx = tid + i * 256;
                const int r = idx >> 3, ch = (idx & 7) * 8;
                CP_ASYNC16(smaddr(&Kn[r * FQH + ch]), &Kgn[(r << 6) + ch]);
                CP_ASYNC16(smaddr(&Vn[r * FQH + ch]), &Vgn[r * NS + ch]);
            }
            CP_COMMIT();
        }

        const __half* Ks = smh + FK_OFF + st * 64 * FQH;
        const __half* Vs = smh + FV_OFF + st * 64 * FQH;

        // Warp-level skip: rows of this warp all above the key range -> masked
        const bool active = (qt * 128 + wBase + 15) >= kt * 64;
        if (active) {
            // ---- S = Q @ K^T  (4 k16 steps over HD=64) ----
            float s[8][4] = {};
#pragma unroll
            for (int kb = 0; kb < 4; kb++) {
                uint2 qlo = *(const uint2*)&Qs[(wBase + gid) * FQH + kb * 16 + 4 * tig];
                uint2 qhi = *(const uint2*)&Qs[(wBase + gid + 8) * FQH + kb * 16 + 4 * tig];
#pragma unroll
                for (int nt = 0; nt < 8; nt++) {
                    uint2 bb = *(const uint2*)&Ks[(nt * 8 + gid) * FQH + kb * 16 + 4 * tig];
                    mma_fp16(s[nt], qlo.x, qhi.x, qlo.y, qhi.y, bb.x, bb.y);
                }
            }

            // ---- causal mask (last two kt tiles only) ----
            if (kt >= 2 * qt) {
#pragma unroll
                for (int nt = 0; nt < 8; nt++) {
                    const int col = kt * 64 + nt * 8 + 2 * tig;
                    if (col > rowG0) s[nt][0] = -1e30f;
                    if (col + 1 > rowG0) s[nt][1] = -1e30f;
                    if (col > rowG0 + 8) s[nt][2] = -1e30f;
                    if (col + 1 > rowG0 + 8) s[nt][3] = -1e30f;
                }
            }

            // ---- online softmax (registers + quad shuffles) ----
            float mx0 = -1e30f, mx1 = -1e30f;
#pragma unroll
            for (int nt = 0; nt < 8; nt++) {
                mx0 = fmaxf(mx0, fmaxf(s[nt][0], s[nt][1]));
                mx1 = fmaxf(mx1, fmaxf(s[nt][2], s[nt][3]));
            }
            mx0 = fmaxf(mx0, __shfl_xor_sync(0xffffffffu, mx0, 1));
            mx0 = fmaxf(mx0, __shfl_xor_sync(0xffffffffu, mx0, 2));
            mx1 = fmaxf(mx1, __shfl_xor_sync(0xffffffffu, mx1, 1));
            mx1 = fmaxf(mx1, __shfl_xor_sync(0xffffffffu, mx1, 2));
            const float mn0 = fmaxf(m0, mx0);
            const float mn1 = fmaxf(m1, mx1);
            const float al0 = __expf(m0 - mn0);
            const float al1 = __expf(m1 - mn1);
            m0 = mn0; m1 = mn1;
            float sum0 = 0.0f, sum1 = 0.0f;
#pragma unroll
            for (int nt = 0; nt < 8; nt++) {
                float p0 = __expf(s[nt][0] - mn0);
                float p1 = __expf(s[nt][1] - mn0);
                float p2 = __expf(s[nt][2] - mn1);
                float p3 = __expf(s[nt][3] - mn1);
                sum0 += p0 + p1;
                sum1 += p2 + p3;
                s[nt][0] = p0; s[nt][1] = p1;
                s[nt][2] = p2; s[nt][3] = p3;
            }
            sum0 += __shfl_xor_sync(0xffffffffu, sum0, 1);
            sum0 += __shfl_xor_sync(0xffffffffu, sum0, 2);
            sum1 += __shfl_xor_sync(0xffffffffu, sum1, 1);
            sum1 += __shfl_xor_sync(0xffffffffu, sum1, 2);
            l0 = l0 * al0 + sum0;
            l1 = l1 * al1 + sum1;

            // ---- O = O*alpha + P @ V  (P packed to half2 in regs) ----
#pragma unroll
            for (int nt = 0; nt < 8; nt++) {
                o[nt][0] *= al0; o[nt][1] *= al0;
                o[nt][2] *= al1; o[nt][3] *= al1;
            }
#pragma unroll
            for (int kb = 0; kb < 4; kb++) {
                const unsigned a0 = h2u(__floats2half2_rn(s[2 * kb][0], s[2 * kb][1]));
                const unsigned a1 = h2u(__floats2half2_rn(s[2 * kb][2], s[2 * kb][3]));
                const unsigned a2 = h2u(__floats2half2_rn(s[2 * kb + 1][0], s[2 * kb + 1][1]));
                const unsigned a3 = h2u(__floats2half2_rn(s[2 * kb + 1][2], s[2 * kb + 1][3]));
#pragma unroll
                for (int nt = 0; nt < 8; nt++) {
                    uint2 bb = *(const uint2*)&Vs[(nt * 8 + gid) * FQH + kb * 16 + 4 * tig];
                    mma_fp16(o[nt], a0, a1, a2, a3, bb.x, bb.y);
                }
            }
        }
    }

    // ---- normalize, store ctx half [B,S,permh(D)] for out_proj ----
    const float i0 = 1.0f / l0;
    const float i1 = 1.0f / l1;
    const int colBase = (h << 6) + 2 * tig;
    __half* row0 = &h_ctx[(size_t)(b * NS + rowG0) * ND];
    __half* row1 = &h_ctx[(size_t)(b * NS + rowG0 + 8) * ND];
#pragma unroll
    for (int nt = 0; nt < 8; nt++) {
        const int c = colBase + nt * 8;
        *(__half2*)&row0[permh(c)] =
            __floats2half2_rn(o[nt][0] * i0, o[nt][1] * i0);
        *(__half2*)&row1[permh(c)] =
            __floats2half2_rn(o[nt][2] * i1, o[nt][3] * i1);
    }
}

extern "C" void kernel_launch(void* const* d_in, const int* in_sizes, int n_in,
                              void* d_out, int out_size) {
    const float* x = (const float*)d_in[0];
    const float* Wq = (const float*)d_in[1];
    const float* bq = (const float*)d_in[2];
    const float* Wk = (const float*)d_in[3];
    const float* bk = (const float*)d_in[4];
    const float* Wv = (const float*)d_in[5];
    const float* bv = (const float*)d_in[6];
    const float* Wo = (const float*)d_in[7];
    const float* bo = (const float*)d_in[8];
    float* out = (float*)d_out;

    cudaFuncSetAttribute(flash_attn_kernel,
                         cudaFuncAttributeMaxDynamicSharedMemorySize,
                         F_SMEM_BYTES);
    cudaFuncSetAttribute(qkv_proj_kernel,
                         cudaFuncAttributeMaxDynamicSharedMemorySize,
                         GEMM_SMEM_BYTES);
    cudaFuncSetAttribute(out_proj_kernel,
                         cudaFuncAttributeMaxDynamicSharedMemorySize,
                         GEMM_SMEM_BYTES);

    // Prep: round + permute x; transpose + round + permute all W
    round_x_kernel<<<MTOT * ND / 1024, 256>>>(x);
    dim3 gw(ND / 32, ND / 32, 4);
    round_w_kernel<<<gw, dim3(32, 8)>>>(Wq, Wk, Wv, Wo);

    dim3 g1(ND / 128, MTOT / 256, 3);
    qkv_proj_kernel<<<g1, 256, GEMM_SMEM_BYTES>>>(bq, bk, bv);

    dim3 g2(NS / 128, NH, NB);
    flash_attn_kernel<<<g2, 256, F_SMEM_BYTES>>>();

    dim3 g3(ND / 128, MTOT / 256);
    out_proj_kernel<<<g3, 256, GEMM_SMEM_BYTES>>>(bo, out);
}

// round 16
// speedup vs baseline: 1.7050x; 1.0346x over previous
#include <cuda_runtime.h>
#include <cuda_fp16.h>
#include <math.h>

#define NB 2
#define NS 2048
#define ND 1024
#define NH 16
#define NHD 64
#define MTOT (NB * NS)   // 4096

#define LOG2E 1.44269504088896f

// Scratch (allocation-free rule: __device__ globals). All half, permh'd k.
__device__ __half h_q[NB * NH * NS * NHD];    // [B,H,S, permh(HD)], ×0.125·log2e
__device__ __half h_k[NB * NH * NS * NHD];    // [B,H,S, permh(HD)]
__device__ __half h_v[NB * NH * NHD * NS];    // [B,H,HD, permh(S)]
__device__ __half h_ctx[NB * NS * ND];        // [M, permh(ND)]
__device__ __half h_xr[MTOT * ND];            // [M, permh(ND)]
__device__ __half h_wr[4][ND * ND];           // [N, permh(ND)] (W^T)

// ---------------------------------------------------------------------------
// helpers
// ---------------------------------------------------------------------------
__device__ __forceinline__ void mma_fp16(float (&c)[4], unsigned a0, unsigned a1,
                                         unsigned a2, unsigned a3, unsigned b0,
                                         unsigned b1) {
    asm volatile(
        "mma.sync.aligned.m16n8k16.row.col.f32.f16.f16.f32 "
        "{%0,%1,%2,%3}, {%4,%5,%6,%7}, {%8,%9}, {%0,%1,%2,%3};\n"
        : "+f"(c[0]), "+f"(c[1]), "+f"(c[2]), "+f"(c[3])
        : "r"(a0), "r"(a1), "r"(a2), "r"(a3), "r"(b0), "r"(b1));
}

__device__ __forceinline__ unsigned h2u(__half2 h) {
    return *reinterpret_cast<unsigned*>(&h);
}

__device__ __forceinline__ unsigned smaddr(const void* p) {
    return (unsigned)__cvta_generic_to_shared(p);
}
#define CP_ASYNC16(dst, src) \
    asm volatile("cp.async.cg.shared.global [%0], [%1], 16;\n" ::"r"(dst), "l"(src))
#define CP_COMMIT() asm volatile("cp.async.commit_group;\n")
#define CP_WAIT(n) asm volatile("cp.async.wait_group %0;\n" ::"n"(n))

// permh: within each 16-block, place k so the fragment quad (2t, 2t+1,
// 2t+8, 2t+9) for quad-thread t is CONTIGUOUS (one 8B LDS per reg pair).
__device__ __forceinline__ int permh(int k) {
    return (k & ~15) | ((((k & 7) >> 1)) << 2) | (k & 1) | (((k >> 3) & 1) << 1);
}

// ---------------------------------------------------------------------------
// Prep kernels: fp16-round + permute (x) / transpose+round+permute (W)
// ---------------------------------------------------------------------------
__global__ void __launch_bounds__(256)
round_x_kernel(const float* __restrict__ x) {
    const int base = (blockIdx.x * 256 + threadIdx.x) * 4;
    float4 v = *(const float4*)&x[base];
    h_xr[permh(base + 0)] = __float2half_rn(v.x);
    h_xr[permh(base + 1)] = __float2half_rn(v.y);
    h_xr[permh(base + 2)] = __float2half_rn(v.z);
    h_xr[permh(base + 3)] = __float2half_rn(v.w);
}

__global__ void __launch_bounds__(256)
round_w_kernel(const float* __restrict__ Wq, const float* __restrict__ Wk,
               const float* __restrict__ Wv, const float* __restrict__ Wo) {
    __shared__ float t[32][33];
    const float* W;
    if (blockIdx.z == 0) W = Wq;
    else if (blockIdx.z == 1) W = Wk;
    else if (blockIdx.z == 2) W = Wv;
    else W = Wo;
    __half* out = &h_wr[blockIdx.z][0];

    const int k0 = blockIdx.x * 32, n0 = blockIdx.y * 32;
    const int tx = threadIdx.x, ty = threadIdx.y;
#pragma unroll
    for (int i = 0; i < 4; i++)
        t[ty + i * 8][tx] = W[(size_t)(k0 + ty + i * 8) * ND + n0 + tx];
    __syncthreads();
#pragma unroll
    for (int i = 0; i < 4; i++)
        out[(size_t)(n0 + ty + i * 8) * ND + k0 + permh(tx)] =
            __float2half_rn(t[tx][ty + i * 8]);
}

// ---------------------------------------------------------------------------
// 256x128x32 FP16 GEMM tile (round-15 proven version, byte-identical).
// ---------------------------------------------------------------------------
#define GSTRH 48
#define GA_H (256 * GSTRH)
#define GB_H (128 * GSTRH)
#define GST_H (GA_H + GB_H)
#define GEMM_SMEM_BYTES (2 * GST_H * 2)

__device__ __forceinline__ void gemm_load_stage(const __half* __restrict__ A,
                                                const __half* __restrict__ Bt,
                                                __half* stage, int mBase,
                                                int nBase, int k0, int tid) {
    __half* sA = stage;
    __half* sB = stage + GA_H;
#pragma unroll
    for (int i = 0; i < 4; i++) {   // A: 256 rows x 4 chunks(16B)
        const int idx = tid + i * 256;
        const int row = idx >> 2, ch = (idx & 3) * 8;
        CP_ASYNC16(smaddr(&sA[row * GSTRH + ch]),
                   &A[(size_t)(mBase + row) * ND + k0 + ch]);
    }
#pragma unroll
    for (int i = 0; i < 2; i++) {   // B: 128 rows x 4 chunks
        const int idx = tid + i * 256;
        const int row = idx >> 2, ch = (idx & 3) * 8;
        CP_ASYNC16(smaddr(&sB[row * GSTRH + ch]),
                   &Bt[(size_t)(nBase + row) * ND + k0 + ch]);
    }
    CP_COMMIT();
}

__device__ __forceinline__ void sgemm_mma(const __half* __restrict__ A,
                                          const __half* __restrict__ Bt,
                                          float (&acc)[4][8][4]) {
    extern __shared__ __half gsm[];

    const int tid = threadIdx.x;
    const int lane = tid & 31;
    const int wid = tid >> 5;
    const int warpM = wid >> 1;   // 0..3 -> 64 rows each
    const int warpN = wid & 1;    // 0..1 -> 64 cols each
    const int gid = lane >> 2;
    const int tig = lane & 3;
    const int mBase = blockIdx.y * 256;
    const int nBase = blockIdx.x * 128;

    gemm_load_stage(A, Bt, gsm, mBase, nBase, 0, tid);

    for (int k0 = 0; k0 < ND; k0 += 32) {
        const int st = (k0 >> 5) & 1;
        CP_WAIT(0);
        __syncthreads();
        if (k0 + 32 < ND)
            gemm_load_stage(A, Bt, gsm + (st ^ 1) * GST_H, mBase, nBase,
                            k0 + 32, tid);

        const __half* As = gsm + st * GST_H;
        const __half* Bs = As + GA_H;
#pragma unroll
        for (int ks = 0; ks < 32; ks += 16) {
            uint2 bf[8];
#pragma unroll
            for (int nt = 0; nt < 8; nt++)
                bf[nt] = *(const uint2*)&Bs[(warpN * 64 + nt * 8 + gid) * GSTRH + ks + 4 * tig];
#pragma unroll
            for (int mt = 0; mt < 4; mt++) {
                const int m = warpM * 64 + mt * 16;
                uint2 lo = *(const uint2*)&As[(m + gid) * GSTRH + ks + 4 * tig];
                uint2 hi = *(const uint2*)&As[(m + gid + 8) * GSTRH + ks + 4 * tig];
#pragma unroll
                for (int nt = 0; nt < 8; nt++)
                    mma_fp16(acc[mt][nt], lo.x, hi.x, lo.y, hi.y,
                             bf[nt].x, bf[nt].y);
            }
        }
    }
}

// QKV projection. Q/K half [B,H,S,permh(HD)]; V half TRANSPOSED
// [B,H,HD,permh(S)]. gridDim.z = 3. Q pre-scaled by 0.125*log2e (exp2 dom).
__global__ void __launch_bounds__(256, 1)
qkv_proj_kernel(const float* __restrict__ bq, const float* __restrict__ bk,
                const float* __restrict__ bv) {
    const __half* Bt;
    const float* bias;
    float sc;
    if (blockIdx.z == 0) { Bt = h_wr[0]; bias = bq; sc = 0.125f * LOG2E; }
    else if (blockIdx.z == 1) { Bt = h_wr[1]; bias = bk; sc = 1.0f; }
    else { Bt = h_wr[2]; bias = bv; sc = 1.0f; }

    float acc[4][8][4] = {};
    sgemm_mma(h_xr, Bt, acc);

    const int lane = threadIdx.x & 31;
    const int wid = threadIdx.x >> 5;
    const int warpM = wid >> 1, warpN = wid & 1;
    const int gid = lane >> 2, tig = lane & 3;
    const int mBase = blockIdx.y * 256, nBase = blockIdx.x * 128;

    if (blockIdx.z < 2) {
        __half* out = (blockIdx.z == 0) ? h_q : h_k;
#pragma unroll
        for (int mt = 0; mt < 4; mt++) {
#pragma unroll
            for (int nt = 0; nt < 8; nt++) {
                const int c = nBase + warpN * 64 + nt * 8 + tig * 2;
                const int h = c >> 6, hd = c & 63;
                const float b0v = bias[c], b1v = bias[c + 1];
#pragma unroll
                for (int half_ = 0; half_ < 2; half_++) {
                    const int r = mBase + warpM * 64 + mt * 16 + gid + half_ * 8;
                    const int b = r >> 11, s = r & 2047;
                    __half2 val = __floats2half2_rn(
                        (acc[mt][nt][half_ * 2 + 0] + b0v) * sc,
                        (acc[mt][nt][half_ * 2 + 1] + b1v) * sc);
                    *(__half2*)&out[(((b * NH + h) * NS + s) << 6) + permh(hd)] =
                        val;
                }
            }
        }
    } else {
        // V: transposed store h_v[((b*NH+h)*NHD + hd)*NS + permh(s)]
#pragma unroll
        for (int mt = 0; mt < 4; mt++) {
#pragma unroll
            for (int nt = 0; nt < 8; nt++) {
                const int c = nBase + warpN * 64 + nt * 8 + tig * 2;
                const int h = c >> 6, hd = c & 63;
                const float b0v = bias[c], b1v = bias[c + 1];
#pragma unroll
                for (int half_ = 0; half_ < 2; half_++) {
                    const int r = mBase + warpM * 64 + mt * 16 + gid + half_ * 8;
                    const int b = r >> 11, s = r & 2047;
                    __half* base =
                        &h_v[(size_t)((b * NH + h) * NHD + hd) * NS + permh(s)];
                    base[0] = __float2half_rn(acc[mt][nt][half_ * 2 + 0] + b0v);
                    base[NS] = __float2half_rn(acc[mt][nt][half_ * 2 + 1] + b1v);
                }
            }
        }
    }
}

// Output projection: out = ctx @ Wo + bo  (f32 output)
__global__ void __launch_bounds__(256, 1)
out_proj_kernel(const float* __restrict__ bo, float* __restrict__ out) {
    float acc[4][8][4] = {};
    sgemm_mma(h_ctx, h_wr[3], acc);

    const int lane = threadIdx.x & 31;
    const int wid = threadIdx.x >> 5;
    const int warpM = wid >> 1, warpN = wid & 1;
    const int gid = lane >> 2, tig = lane & 3;
    const int mBase = blockIdx.y * 256, nBase = blockIdx.x * 128;

#pragma unroll
    for (int mt = 0; mt < 4; mt++) {
#pragma unroll
        for (int nt = 0; nt < 8; nt++) {
            const int c = nBase + warpN * 64 + nt * 8 + tig * 2;
            const float b0v = bo[c], b1v = bo[c + 1];
#pragma unroll
            for (int half_ = 0; half_ < 2; half_++) {
                const int r = mBase + warpM * 64 + mt * 16 + gid + half_ * 8;
                float2 val;
                val.x = acc[mt][nt][half_ * 2 + 0] + b0v;
                val.y = acc[mt][nt][half_ * 2 + 1] + b1v;
                *(float2*)&out[(size_t)r * ND + c] = val;
            }
        }
    }
}

// ---------------------------------------------------------------------------
// FlashAttention-2 fp16, exp2-domain softmax, deferred quad l-reduction.
// Q[128][80] | K[2][64][80] | V[2][64][80] halves = 60 KB, 2 CTAs/SM.
// ---------------------------------------------------------------------------
#define FQH 80
#define FQ_OFF 0
#define FK_OFF (128 * FQH)
#define FV_OFF (FK_OFF + 2 * 64 * FQH)
#define F_SMEM_HALVES (FV_OFF + 2 * 64 * FQH)
#define F_SMEM_BYTES (F_SMEM_HALVES * 2)

__global__ void __launch_bounds__(256, 2) flash_attn_kernel() {
    extern __shared__ __half smh[];
    __half* Qs = smh + FQ_OFF;

    const int tid = threadIdx.x;
    const int lane = tid & 31;
    const int wid = tid >> 5;        // 0..7, 16 query rows each
    const int gid = lane >> 2;       // 0..7
    const int tig = lane & 3;        // 0..3

    const int qt = gridDim.x - 1 - blockIdx.x;  // heavy tiles first
    const int h = blockIdx.y, b = blockIdx.z;
    const int bhBase = ((b * NH + h) * NS) << 6;
    const __half* Qg = h_q + bhBase;
    const __half* Kg = h_k + bhBase;
    const __half* Vgt = h_v + bhBase;  // [HD][permh(S)] block

    // prologue: async-load Q tile + K0 + V0 (one group)
#pragma unroll
    for (int i = 0; i < 4; i++) {
        const int idx = tid + i * 256;
        const int r = idx >> 3, ch = (idx & 7) * 8;
        CP_ASYNC16(smaddr(&Qs[r * FQH + ch]), &Qg[((qt * 128 + r) << 6) + ch]);
    }
#pragma unroll
    for (int i = 0; i < 2; i++) {
        const int idx = tid + i * 256;
        const int r = idx >> 3, ch = (idx & 7) * 8;
        CP_ASYNC16(smaddr(&smh[FK_OFF + r * FQH + ch]), &Kg[(r << 6) + ch]);
        CP_ASYNC16(smaddr(&smh[FV_OFF + r * FQH + ch]), &Vgt[r * NS + ch]);
    }
    CP_COMMIT();

    float o[8][4] = {};
    float m0 = -1e30f, m1 = -1e30f;
    float l0 = 0.0f, l1 = 0.0f;      // PER-THREAD PARTIALS (quad-reduced at end)
    const int wBase = wid * 16;
    const int rowG0 = qt * 128 + wBase + gid;
    const int ktMax = 2 * qt + 1;

    for (int kt = 0; kt <= ktMax; kt++) {
        const int st = kt & 1;
        CP_WAIT(0);
        __syncthreads();
        if (kt < ktMax) {
            __half* Kn = smh + FK_OFF + (st ^ 1) * 64 * FQH;
            __half* Vn = smh + FV_OFF + (st ^ 1) * 64 * FQH;
            const __half* Kgn = Kg + (((kt + 1) * 64) << 6);
            const __half* Vgn = Vgt + (kt + 1) * 64;
#pragma unroll
            for (int i = 0; i < 2; i++) {
                const int idx = tid + i * 256;
                const int r = idx >> 3, ch = (idx & 7) * 8;
                CP_ASYNC16(smaddr(&Kn[r * FQH + ch]), &Kgn[(r << 6) + ch]);
                CP_ASYNC16(smaddr(&Vn[r * FQH + ch]), &Vgn[r * NS + ch]);
            }
            CP_COMMIT();
        }

        const __half* Ks = smh + FK_OFF + st * 64 * FQH;
        const __half* Vs = smh + FV_OFF + st * 64 * FQH;

        // Warp-level skip: rows of this warp all above the key range -> masked
        const bool active = (qt * 128 + wBase + 15) >= kt * 64;
        if (active) {
            // ---- S = Q @ K^T  (log2 units; Q pre-scaled by 0.125*log2e) ----
            float s[8][4] = {};
#pragma unroll
            for (int kb = 0; kb < 4; kb++) {
                uint2 qlo = *(const uint2*)&Qs[(wBase + gid) * FQH + kb * 16 + 4 * tig];
                uint2 qhi = *(const uint2*)&Qs[(wBase + gid + 8) * FQH + kb * 16 + 4 * tig];
#pragma unroll
                for (int nt = 0; nt < 8; nt++) {
                    uint2 bb = *(const uint2*)&Ks[(nt * 8 + gid) * FQH + kb * 16 + 4 * tig];
                    mma_fp16(s[nt], qlo.x, qhi.x, qlo.y, qhi.y, bb.x, bb.y);
                }
            }

            // ---- causal mask (last two kt tiles only) ----
            if (kt >= 2 * qt) {
#pragma unroll
                for (int nt = 0; nt < 8; nt++) {
                    const int col = kt * 64 + nt * 8 + 2 * tig;
                    if (col > rowG0) s[nt][0] = -1e30f;
                    if (col + 1 > rowG0) s[nt][1] = -1e30f;
                    if (col > rowG0 + 8) s[nt][2] = -1e30f;
                    if (col + 1 > rowG0 + 8) s[nt][3] = -1e30f;
                }
            }

            // ---- online softmax (exp2 domain; max shuffles only) ----
            float mx0 = -1e30f, mx1 = -1e30f;
#pragma unroll
            for (int nt = 0; nt < 8; nt++) {
                mx0 = fmaxf(mx0, fmaxf(s[nt][0], s[nt][1]));
                mx1 = fmaxf(mx1, fmaxf(s[nt][2], s[nt][3]));
            }
            mx0 = fmaxf(mx0, __shfl_xor_sync(0xffffffffu, mx0, 1));
            mx0 = fmaxf(mx0, __shfl_xor_sync(0xffffffffu, mx0, 2));
            mx1 = fmaxf(mx1, __shfl_xor_sync(0xffffffffu, mx1, 1));
            mx1 = fmaxf(mx1, __shfl_xor_sync(0xffffffffu, mx1, 2));
            const float mn0 = fmaxf(m0, mx0);
            const float mn1 = fmaxf(m1, mx1);
            const float al0 = exp2f(m0 - mn0);
            const float al1 = exp2f(m1 - mn1);
            m0 = mn0; m1 = mn1;
            float sum0 = 0.0f, sum1 = 0.0f;
#pragma unroll
            for (int nt = 0; nt < 8; nt++) {
                float p0 = exp2f(s[nt][0] - mn0);
                float p1 = exp2f(s[nt][1] - mn0);
                float p2 = exp2f(s[nt][2] - mn1);
                float p3 = exp2f(s[nt][3] - mn1);
                sum0 += p0 + p1;
                sum1 += p2 + p3;
                s[nt][0] = p0; s[nt][1] = p1;
                s[nt][2] = p2; s[nt][3] = p3;
            }
            // per-thread partial l (alpha is quad-uniform -> linearity holds)
            l0 = l0 * al0 + sum0;
            l1 = l1 * al1 + sum1;

            // ---- O = O*alpha + P @ V  (P packed to half2 in regs) ----
#pragma unroll
            for (int nt = 0; nt < 8; nt++) {
                o[nt][0] *= al0; o[nt][1] *= al0;
                o[nt][2] *= al1; o[nt][3] *= al1;
            }
#pragma unroll
            for (int kb = 0; kb < 4; kb++) {
                const unsigned a0 = h2u(__floats2half2_rn(s[2 * kb][0], s[2 * kb][1]));
                const unsigned a1 = h2u(__floats2half2_rn(s[2 * kb][2], s[2 * kb][3]));
                const unsigned a2 = h2u(__floats2half2_rn(s[2 * kb + 1][0], s[2 * kb + 1][1]));
                const unsigned a3 = h2u(__floats2half2_rn(s[2 * kb + 1][2], s[2 * kb + 1][3]));
#pragma unroll
                for (int nt = 0; nt < 8; nt++) {
                    uint2 bb = *(const uint2*)&Vs[(nt * 8 + gid) * FQH + kb * 16 + 4 * tig];
                    mma_fp16(o[nt], a0, a1, a2, a3, bb.x, bb.y);
                }
            }
        }
    }

    // ---- final quad reduction of l (deferred from the loop) ----
    l0 += __shfl_xor_sync(0xffffffffu, l0, 1);
    l0 += __shfl_xor_sync(0xffffffffu, l0, 2);
    l1 += __shfl_xor_sync(0xffffffffu, l1, 1);
    l1 += __shfl_xor_sync(0xffffffffu, l1, 2);

    // ---- normalize, store ctx half [B,S,permh(D)] for out_proj ----
    const float i0 = 1.0f / l0;
    const float i1 = 1.0f / l1;
    const int colBase = (h << 6) + 2 * tig;
    __half* row0 = &h_ctx[(size_t)(b * NS + rowG0) * ND];
    __half* row1 = &h_ctx[(size_t)(b * NS + rowG0 + 8) * ND];
#pragma unroll
    for (int nt = 0; nt < 8; nt++) {
        const int c = colBase + nt * 8;
        *(__half2*)&row0[permh(c)] =
            __floats2half2_rn(o[nt][0] * i0, o[nt][1] * i0);
        *(__half2*)&row1[permh(c)] =
            __floats2half2_rn(o[nt][2] * i1, o[nt][3] * i1);
    }
}

extern "C" void kernel_launch(void* const* d_in, const int* in_sizes, int n_in,
                              void* d_out, int out_size) {
    const float* x = (const float*)d_in[0];
    const float* Wq = (const float*)d_in[1];
    const float* bq = (const float*)d_in[2];
    const float* Wk = (const float*)d_in[3];
    const float* bk = (const float*)d_in[4];
    const float* Wv = (const float*)d_in[5];
    const float* bv = (const float*)d_in[6];
    const float* Wo = (const float*)d_in[7];
    const float* bo = (const float*)d_in[8];
    float* out = (float*)d_out;

    cudaFuncSetAttribute(flash_attn_kernel,
                         cudaFuncAttributeMaxDynamicSharedMemorySize,
                         F_SMEM_BYTES);
    cudaFuncSetAttribute(qkv_proj_kernel,
                         cudaFuncAttributeMaxDynamicSharedMemorySize,
                         GEMM_SMEM_BYTES);
    cudaFuncSetAttribute(out_proj_kernel,
                         cudaFuncAttributeMaxDynamicSharedMemorySize,
                         GEMM_SMEM_BYTES);

    // Prep: round + permute x; transpose + round + permute all W
    round_x_kernel<<<MTOT * ND / 1024, 256>>>(x);
    dim3 gw(ND / 32, ND / 32, 4);
    round_w_kernel<<<gw, dim3(32, 8)>>>(Wq, Wk, Wv, Wo);

    dim3 g1(ND / 128, MTOT / 256, 3);
    qkv_proj_kernel<<<g1, 256, GEMM_SMEM_BYTES>>>(bq, bk, bv);

    dim3 g2(NS / 128, NH, NB);
    flash_attn_kernel<<<g2, 256, F_SMEM_BYTES>>>();

    dim3 g3(ND / 128, MTOT / 256);
    out_proj_kernel<<<g3, 256, GEMM_SMEM_BYTES>>>(bo, out);
}

// round 17
// speedup vs baseline: 1.7325x; 1.0161x over previous
#include <cuda_runtime.h>
#include <cuda_fp16.h>
#include <math.h>

#define NB 2
#define NS 2048
#define ND 1024
#define NH 16
#define NHD 64
#define MTOT (NB * NS)   // 4096

#define LOG2E 1.44269504088896f

// Scratch (allocation-free rule: __device__ globals). All half, permh'd k.
__device__ __half h_q[NB * NH * NS * NHD];    // [B,H,S, permh(HD)], ×0.125·log2e
__device__ __half h_k[NB * NH * NS * NHD];    // [B,H,S, permh(HD)]
__device__ __half h_v[NB * NH * NHD * NS];    // [B,H,HD, permh(S)]
__device__ __half h_ctx[NB * NS * ND];        // [M, permh(ND)]
__device__ __half h_xr[MTOT * ND];            // [M, permh(ND)]
__device__ __half h_wr[4][ND * ND];           // [N, permh(ND)] (W^T)

// ---------------------------------------------------------------------------
// helpers
// ---------------------------------------------------------------------------
__device__ __forceinline__ void mma_fp16(float (&c)[4], unsigned a0, unsigned a1,
                                         unsigned a2, unsigned a3, unsigned b0,
                                         unsigned b1) {
    asm volatile(
        "mma.sync.aligned.m16n8k16.row.col.f32.f16.f16.f32 "
        "{%0,%1,%2,%3}, {%4,%5,%6,%7}, {%8,%9}, {%0,%1,%2,%3};\n"
        : "+f"(c[0]), "+f"(c[1]), "+f"(c[2]), "+f"(c[3])
        : "r"(a0), "r"(a1), "r"(a2), "r"(a3), "r"(b0), "r"(b1));
}

__device__ __forceinline__ unsigned h2u(__half2 h) {
    return *reinterpret_cast<unsigned*>(&h);
}

__device__ __forceinline__ unsigned ex2_h2(unsigned x) {
    unsigned r;
    asm("ex2.approx.f16x2 %0, %1;" : "=r"(r) : "r"(x));
    return r;
}

__device__ __forceinline__ unsigned smaddr(const void* p) {
    return (unsigned)__cvta_generic_to_shared(p);
}
#define CP_ASYNC16(dst, src) \
    asm volatile("cp.async.cg.shared.global [%0], [%1], 16;\n" ::"r"(dst), "l"(src))
#define CP_COMMIT() asm volatile("cp.async.commit_group;\n")
#define CP_WAIT(n) asm volatile("cp.async.wait_group %0;\n" ::"n"(n))

#define ONES_H2 0x3C003C00u   // half2(1.0, 1.0)

// permh: within each 16-block, place k so the fragment quad (2t, 2t+1,
// 2t+8, 2t+9) for quad-thread t is CONTIGUOUS (one 8B LDS per reg pair).
__device__ __forceinline__ int permh(int k) {
    return (k & ~15) | ((((k & 7) >> 1)) << 2) | (k & 1) | (((k >> 3) & 1) << 1);
}

// ---------------------------------------------------------------------------
// Prep kernels: fp16-round + permute (x) / transpose+round+permute (W)
// ---------------------------------------------------------------------------
__global__ void __launch_bounds__(256)
round_x_kernel(const float* __restrict__ x) {
    const int base = (blockIdx.x * 256 + threadIdx.x) * 4;
    float4 v = *(const float4*)&x[base];
    h_xr[permh(base + 0)] = __float2half_rn(v.x);
    h_xr[permh(base + 1)] = __float2half_rn(v.y);
    h_xr[permh(base + 2)] = __float2half_rn(v.z);
    h_xr[permh(base + 3)] = __float2half_rn(v.w);
}

__global__ void __launch_bounds__(256)
round_w_kernel(const float* __restrict__ Wq, const float* __restrict__ Wk,
               const float* __restrict__ Wv, const float* __restrict__ Wo) {
    __shared__ float t[32][33];
    const float* W;
    if (blockIdx.z == 0) W = Wq;
    else if (blockIdx.z == 1) W = Wk;
    else if (blockIdx.z == 2) W = Wv;
    else W = Wo;
    __half* out = &h_wr[blockIdx.z][0];

    const int k0 = blockIdx.x * 32, n0 = blockIdx.y * 32;
    const int tx = threadIdx.x, ty = threadIdx.y;
#pragma unroll
    for (int i = 0; i < 4; i++)
        t[ty + i * 8][tx] = W[(size_t)(k0 + ty + i * 8) * ND + n0 + tx];
    __syncthreads();
#pragma unroll
    for (int i = 0; i < 4; i++)
        out[(size_t)(n0 + ty + i * 8) * ND + k0 + permh(tx)] =
            __float2half_rn(t[tx][ty + i * 8]);
}

// ---------------------------------------------------------------------------
// 256x128x32 FP16 GEMM tile (round-15 proven version, byte-identical).
// ---------------------------------------------------------------------------
#define GSTRH 48
#define GA_H (256 * GSTRH)
#define GB_H (128 * GSTRH)
#define GST_H (GA_H + GB_H)
#define GEMM_SMEM_BYTES (2 * GST_H * 2)

__device__ __forceinline__ void gemm_load_stage(const __half* __restrict__ A,
                                                const __half* __restrict__ Bt,
                                                __half* stage, int mBase,
                                                int nBase, int k0, int tid) {
    __half* sA = stage;
    __half* sB = stage + GA_H;
#pragma unroll
    for (int i = 0; i < 4; i++) {   // A: 256 rows x 4 chunks(16B)
        const int idx = tid + i * 256;
        const int row = idx >> 2, ch = (idx & 3) * 8;
        CP_ASYNC16(smaddr(&sA[row * GSTRH + ch]),
                   &A[(size_t)(mBase + row) * ND + k0 + ch]);
    }
#pragma unroll
    for (int i = 0; i < 2; i++) {   // B: 128 rows x 4 chunks
        const int idx = tid + i * 256;
        const int row = idx >> 2, ch = (idx & 3) * 8;
        CP_ASYNC16(smaddr(&sB[row * GSTRH + ch]),
                   &Bt[(size_t)(nBase + row) * ND + k0 + ch]);
    }
    CP_COMMIT();
}

__device__ __forceinline__ void sgemm_mma(const __half* __restrict__ A,
                                          const __half* __restrict__ Bt,
                                          float (&acc)[4][8][4]) {
    extern __shared__ __half gsm[];

    const int tid = threadIdx.x;
    const int lane = tid & 31;
    const int wid = tid >> 5;
    const int warpM = wid >> 1;   // 0..3 -> 64 rows each
    const int warpN = wid & 1;    // 0..1 -> 64 cols each
    const int gid = lane >> 2;
    const int tig = lane & 3;
    const int mBase = blockIdx.y * 256;
    const int nBase = blockIdx.x * 128;

    gemm_load_stage(A, Bt, gsm, mBase, nBase, 0, tid);

    for (int k0 = 0; k0 < ND; k0 += 32) {
        const int st = (k0 >> 5) & 1;
        CP_WAIT(0);
        __syncthreads();
        if (k0 + 32 < ND)
            gemm_load_stage(A, Bt, gsm + (st ^ 1) * GST_H, mBase, nBase,
                            k0 + 32, tid);

        const __half* As = gsm + st * GST_H;
        const __half* Bs = As + GA_H;
#pragma unroll
        for (int ks = 0; ks < 32; ks += 16) {
            uint2 bf[8];
#pragma unroll
            for (int nt = 0; nt < 8; nt++)
                bf[nt] = *(const uint2*)&Bs[(warpN * 64 + nt * 8 + gid) * GSTRH + ks + 4 * tig];
#pragma unroll
            for (int mt = 0; mt < 4; mt++) {
                const int m = warpM * 64 + mt * 16;
                uint2 lo = *(const uint2*)&As[(m + gid) * GSTRH + ks + 4 * tig];
                uint2 hi = *(const uint2*)&As[(m + gid + 8) * GSTRH + ks + 4 * tig];
#pragma unroll
                for (int nt = 0; nt < 8; nt++)
                    mma_fp16(acc[mt][nt], lo.x, hi.x, lo.y, hi.y,
                             bf[nt].x, bf[nt].y);
            }
        }
    }
}

// QKV projection. Q/K half [B,H,S,permh(HD)]; V half TRANSPOSED
// [B,H,HD,permh(S)]. gridDim.z = 3. Q pre-scaled by 0.125*log2e (exp2 dom).
__global__ void __launch_bounds__(256, 1)
qkv_proj_kernel(const float* __restrict__ bq, const float* __restrict__ bk,
                const float* __restrict__ bv) {
    const __half* Bt;
    const float* bias;
    float sc;
    if (blockIdx.z == 0) { Bt = h_wr[0]; bias = bq; sc = 0.125f * LOG2E; }
    else if (blockIdx.z == 1) { Bt = h_wr[1]; bias = bk; sc = 1.0f; }
    else { Bt = h_wr[2]; bias = bv; sc = 1.0f; }

    float acc[4][8][4] = {};
    sgemm_mma(h_xr, Bt, acc);

    const int lane = threadIdx.x & 31;
    const int wid = threadIdx.x >> 5;
    const int warpM = wid >> 1, warpN = wid & 1;
    const int gid = lane >> 2, tig = lane & 3;
    const int mBase = blockIdx.y * 256, nBase = blockIdx.x * 128;

    if (blockIdx.z < 2) {
        __half* out = (blockIdx.z == 0) ? h_q : h_k;
#pragma unroll
        for (int mt = 0; mt < 4; mt++) {
#pragma unroll
            for (int nt = 0; nt < 8; nt++) {
                const int c = nBase + warpN * 64 + nt * 8 + tig * 2;
                const int h = c >> 6, hd = c & 63;
                const float b0v = bias[c], b1v = bias[c + 1];
#pragma unroll
                for (int half_ = 0; half_ < 2; half_++) {
                    const int r = mBase + warpM * 64 + mt * 16 + gid + half_ * 8;
                    const int b = r >> 11, s = r & 2047;
                    __half2 val = __floats2half2_rn(
                        (acc[mt][nt][half_ * 2 + 0] + b0v) * sc,
                        (acc[mt][nt][half_ * 2 + 1] + b1v) * sc);
                    *(__half2*)&out[(((b * NH + h) * NS + s) << 6) + permh(hd)] =
                        val;
                }
            }
        }
    } else {
        // V: transposed store h_v[((b*NH+h)*NHD + hd)*NS + permh(s)]
#pragma unroll
        for (int mt = 0; mt < 4; mt++) {
#pragma unroll
            for (int nt = 0; nt < 8; nt++) {
                const int c = nBase + warpN * 64 + nt * 8 + tig * 2;
                const int h = c >> 6, hd = c & 63;
                const float b0v = bias[c], b1v = bias[c + 1];
#pragma unroll
                for (int half_ = 0; half_ < 2; half_++) {
                    const int r = mBase + warpM * 64 + mt * 16 + gid + half_ * 8;
                    const int b = r >> 11, s = r & 2047;
                    __half* base =
                        &h_v[(size_t)((b * NH + h) * NHD + hd) * NS + permh(s)];
                    base[0] = __float2half_rn(acc[mt][nt][half_ * 2 + 0] + b0v);
                    base[NS] = __float2half_rn(acc[mt][nt][half_ * 2 + 1] + b1v);
                }
            }
        }
    }
}

// Output projection: out = ctx @ Wo + bo  (f32 output)
__global__ void __launch_bounds__(256, 1)
out_proj_kernel(const float* __restrict__ bo, float* __restrict__ out) {
    float acc[4][8][4] = {};
    sgemm_mma(h_ctx, h_wr[3], acc);

    const int lane = threadIdx.x & 31;
    const int wid = threadIdx.x >> 5;
    const int warpM = wid >> 1, warpN = wid & 1;
    const int gid = lane >> 2, tig = lane & 3;
    const int mBase = blockIdx.y * 256, nBase = blockIdx.x * 128;

#pragma unroll
    for (int mt = 0; mt < 4; mt++) {
#pragma unroll
        for (int nt = 0; nt < 8; nt++) {
            const int c = nBase + warpN * 64 + nt * 8 + tig * 2;
            const float b0v = bo[c], b1v = bo[c + 1];
#pragma unroll
            for (int half_ = 0; half_ < 2; half_++) {
                const int r = mBase + warpM * 64 + mt * 16 + gid + half_ * 8;
                float2 val;
                val.x = acc[mt][nt][half_ * 2 + 0] + b0v;
                val.y = acc[mt][nt][half_ * 2 + 1] + b1v;
                *(float2*)&out[(size_t)r * ND + c] = val;
            }
        }
    }
}

// ---------------------------------------------------------------------------
// FlashAttention-2 fp16. exp2 via f16x2 MUFU (half the EX2 pressure);
// row-sum l via ones-column mma (exact f32, no sum chain, no shuffles).
// Q[128][80] | K[2][64][80] | V[2][64][80] halves = 60 KB, 2 CTAs/SM.
// ---------------------------------------------------------------------------
#define FQH 80
#define FQ_OFF 0
#define FK_OFF (128 * FQH)
#define FV_OFF (FK_OFF + 2 * 64 * FQH)
#define F_SMEM_HALVES (FV_OFF + 2 * 64 * FQH)
#define F_SMEM_BYTES (F_SMEM_HALVES * 2)

__global__ void __launch_bounds__(256, 2) flash_attn_kernel() {
    extern __shared__ __half smh[];
    __half* Qs = smh + FQ_OFF;

    const int tid = threadIdx.x;
    const int lane = tid & 31;
    const int wid = tid >> 5;        // 0..7, 16 query rows each
    const int gid = lane >> 2;       // 0..7
    const int tig = lane & 3;        // 0..3

    const int qt = gridDim.x - 1 - blockIdx.x;  // heavy tiles first
    const int h = blockIdx.y, b = blockIdx.z;
    const int bhBase = ((b * NH + h) * NS) << 6;
    const __half* Qg = h_q + bhBase;
    const __half* Kg = h_k + bhBase;
    const __half* Vgt = h_v + bhBase;  // [HD][permh(S)] block

    // prologue: async-load Q tile + K0 + V0 (one group)
#pragma unroll
    for (int i = 0; i < 4; i++) {
        const int idx = tid + i * 256;
        const int r = idx >> 3, ch = (idx & 7) * 8;
        CP_ASYNC16(smaddr(&Qs[r * FQH + ch]), &Qg[((qt * 128 + r) << 6) + ch]);
    }
#pragma unroll
    for (int i = 0; i < 2; i++) {
        const int idx = tid + i * 256;
        const int r = idx >> 3, ch = (idx & 7) * 8;
        CP_ASYNC16(smaddr(&smh[FK_OFF + r * FQH + ch]), &Kg[(r << 6) + ch]);
        CP_ASYNC16(smaddr(&smh[FV_OFF + r * FQH + ch]), &Vgt[r * NS + ch]);
    }
    CP_COMMIT();

    float o[8][4] = {};
    float lacc[4] = {};              // ones-mma accumulator: [0]=row gid, [2]=row gid+8
    float m0 = -1e30f, m1 = -1e30f;
    const int wBase = wid * 16;
    const int rowG0 = qt * 128 + wBase + gid;
    const int ktMax = 2 * qt + 1;

    for (int kt = 0; kt <= ktMax; kt++) {
        const int st = kt & 1;
        CP_WAIT(0);
        __syncthreads();
        if (kt < ktMax) {
            __half* Kn = smh + FK_OFF + (st ^ 1) * 64 * FQH;
            __half* Vn = smh + FV_OFF + (st ^ 1) * 64 * FQH;
            const __half* Kgn = Kg + (((kt + 1) * 64) << 6);
            const __half* Vgn = Vgt + (kt + 1) * 64;
#pragma unroll
            for (int i = 0; i < 2; i++) {
                const int idx = tid + i * 256;
                const int r = idx >> 3, ch = (idx & 7) * 8;
                CP_ASYNC16(smaddr(&Kn[r * FQH + ch]), &Kgn[(r << 6) + ch]);
                CP_ASYNC16(smaddr(&Vn[r * FQH + ch]), &Vgn[r * NS + ch]);
            }
            CP_COMMIT();
        }

        const __half* Ks = smh + FK_OFF + st * 64 * FQH;
        const __half* Vs = smh + FV_OFF + st * 64 * FQH;

        // Warp-level skip: rows of this warp all above the key range -> masked
        const bool active = (qt * 128 + wBase + 15) >= kt * 64;
        if (active) {
            // ---- S = Q @ K^T  (log2 units; Q pre-scaled by 0.125*log2e) ----
            float s[8][4] = {};
#pragma unroll
            for (int kb = 0; kb < 4; kb++) {
                uint2 qlo = *(const uint2*)&Qs[(wBase + gid) * FQH + kb * 16 + 4 * tig];
                uint2 qhi = *(const uint2*)&Qs[(wBase + gid + 8) * FQH + kb * 16 + 4 * tig];
#pragma unroll
                for (int nt = 0; nt < 8; nt++) {
                    uint2 bb = *(const uint2*)&Ks[(nt * 8 + gid) * FQH + kb * 16 + 4 * tig];
                    mma_fp16(s[nt], qlo.x, qhi.x, qlo.y, qhi.y, bb.x, bb.y);
                }
            }

            // ---- causal mask (last two kt tiles only) ----
            if (kt >= 2 * qt) {
#pragma unroll
                for (int nt = 0; nt < 8; nt++) {
                    const int col = kt * 64 + nt * 8 + 2 * tig;
                    if (col > rowG0) s[nt][0] = -1e30f;
                    if (col + 1 > rowG0) s[nt][1] = -1e30f;
                    if (col > rowG0 + 8) s[nt][2] = -1e30f;
                    if (col + 1 > rowG0 + 8) s[nt][3] = -1e30f;
                }
            }

            // ---- online softmax: max (shfl) then P = exp2 via f16x2 MUFU ----
            float mx0 = -1e30f, mx1 = -1e30f;
#pragma unroll
            for (int nt = 0; nt < 8; nt++) {
                mx0 = fmaxf(mx0, fmaxf(s[nt][0], s[nt][1]));
                mx1 = fmaxf(mx1, fmaxf(s[nt][2], s[nt][3]));
            }
            mx0 = fmaxf(mx0, __shfl_xor_sync(0xffffffffu, mx0, 1));
            mx0 = fmaxf(mx0, __shfl_xor_sync(0xffffffffu, mx0, 2));
            mx1 = fmaxf(mx1, __shfl_xor_sync(0xffffffffu, mx1, 1));
            mx1 = fmaxf(mx1, __shfl_xor_sync(0xffffffffu, mx1, 2));
            const float mn0 = fmaxf(m0, mx0);
            const float mn1 = fmaxf(m1, mx1);
            const float al0 = exp2f(m0 - mn0);
            const float al1 = exp2f(m1 - mn1);
            m0 = mn0; m1 = mn1;

            unsigned p01[8], p23[8];   // P in half2 fragment form
#pragma unroll
            for (int nt = 0; nt < 8; nt++) {
                p01[nt] = ex2_h2(
                    h2u(__floats2half2_rn(s[nt][0] - mn0, s[nt][1] - mn0)));
                p23[nt] = ex2_h2(
                    h2u(__floats2half2_rn(s[nt][2] - mn1, s[nt][3] - mn1)));
            }

            // ---- rescale accumulators ----
#pragma unroll
            for (int nt = 0; nt < 8; nt++) {
                o[nt][0] *= al0; o[nt][1] *= al0;
                o[nt][2] *= al1; o[nt][3] *= al1;
            }
            lacc[0] *= al0; lacc[1] *= al0;
            lacc[2] *= al1; lacc[3] *= al1;

            // ---- l += P @ ones (exact f32 row-sum of the half P) ----
#pragma unroll
            for (int kb = 0; kb < 4; kb++)
                mma_fp16(lacc, p01[2 * kb], p23[2 * kb], p01[2 * kb + 1],
                         p23[2 * kb + 1], ONES_H2, ONES_H2);

            // ---- O += P @ V ----
#pragma unroll
            for (int kb = 0; kb < 4; kb++) {
                const unsigned a0 = p01[2 * kb];
                const unsigned a1 = p23[2 * kb];
                const unsigned a2 = p01[2 * kb + 1];
                const unsigned a3 = p23[2 * kb + 1];
#pragma unroll
                for (int nt = 0; nt < 8; nt++) {
                    uint2 bb = *(const uint2*)&Vs[(nt * 8 + gid) * FQH + kb * 16 + 4 * tig];
                    mma_fp16(o[nt], a0, a1, a2, a3, bb.x, bb.y);
                }
            }
        }
    }

    // ---- normalize, store ctx half [B,S,permh(D)] for out_proj ----
    const float i0 = 1.0f / lacc[0];
    const float i1 = 1.0f / lacc[2];
    const int colBase = (h << 6) + 2 * tig;
    __half* row0 = &h_ctx[(size_t)(b * NS + rowG0) * ND];
    __half* row1 = &h_ctx[(size_t)(b * NS + rowG0 + 8) * ND];
#pragma unroll
    for (int nt = 0; nt < 8; nt++) {
        const int c = colBase + nt * 8;
        *(__half2*)&row0[permh(c)] =
            __floats2half2_rn(o[nt][0] * i0, o[nt][1] * i0);
        *(__half2*)&row1[permh(c)] =
            __floats2half2_rn(o[nt][2] * i1, o[nt][3] * i1);
    }
}

extern "C" void kernel_launch(void* const* d_in, const int* in_sizes, int n_in,
                              void* d_out, int out_size) {
    const float* x = (const float*)d_in[0];
    const float* Wq = (const float*)d_in[1];
    const float* bq = (const float*)d_in[2];
    const float* Wk = (const float*)d_in[3];
    const float* bk = (const float*)d_in[4];
    const float* Wv = (const float*)d_in[5];
    const float* bv = (const float*)d_in[6];
    const float* Wo = (const float*)d_in[7];
    const float* bo = (const float*)d_in[8];
    float* out = (float*)d_out;

    cudaFuncSetAttribute(flash_attn_kernel,
                         cudaFuncAttributeMaxDynamicSharedMemorySize,
                         F_SMEM_BYTES);
    cudaFuncSetAttribute(qkv_proj_kernel,
                         cudaFuncAttributeMaxDynamicSharedMemorySize,
                         GEMM_SMEM_BYTES);
    cudaFuncSetAttribute(out_proj_kernel,
                         cudaFuncAttributeMaxDynamicSharedMemorySize,
                         GEMM_SMEM_BYTES);

    // Prep: round + permute x; transpose + round + permute all W
    round_x_kernel<<<MTOT * ND / 1024, 256>>>(x);
    dim3 gw(ND / 32, ND / 32, 4);
    round_w_kernel<<<gw, dim3(32, 8)>>>(Wq, Wk, Wv, Wo);

    dim3 g1(ND / 128, MTOT / 256, 3);
    qkv_proj_kernel<<<g1, 256, GEMM_SMEM_BYTES>>>(bq, bk, bv);

    dim3 g2(NS / 128, NH, NB);
    flash_attn_kernel<<<g2, 256, F_SMEM_BYTES>>>();

    dim3 g3(ND / 128, MTOT / 256);
    out_proj_kernel<<<g3, 256, GEMM_SMEM_BYTES>>>(bo, out);
}